// round 5
// baseline (speedup 1.0000x reference)
#include <cuda_runtime.h>
#include <cuda_bf16.h>

// LandmarksLoss: mean((pred - true)^2), true = windowed 128x128 bell table.
// Single fused kernel: one CTA per (b,l) image, row-structured streaming loop
// (warp<->row so the bell-window branch is warp-uniform and hoisted per row),
// deterministic last-block final reduction via atomic counter.

#define H_DIM   224
#define W_DIM   224
#define ROWF4   (W_DIM / 4)            // 56 float4 per row
#define THREADS 256
#define NWARP   (THREADS / 32)         // 8
#define ROWS_PW (H_DIM / NWARP)        // 28 rows per warp
#define MAX_BL  4096
#define DELTA   128
#define HALF    64

__device__ float        g_partials[MAX_BL];
__device__ unsigned int g_count = 0;

__device__ __forceinline__ float blockReduce(float v, float* s)
{
    #pragma unroll
    for (int off = 16; off > 0; off >>= 1)
        v += __shfl_down_sync(0xFFFFFFFFu, v, off);
    const int lane = threadIdx.x & 31;
    const int wid  = threadIdx.x >> 5;
    if (lane == 0) s[wid] = v;
    __syncthreads();
    if (wid == 0) {
        v = (lane < NWARP) ? s[lane] : 0.0f;
        #pragma unroll
        for (int off = NWARP / 2; off > 0; off >>= 1)
            v += __shfl_down_sync(0xFFFFFFFFu, v, off);
    }
    return v;  // valid in thread 0
}

__global__ void __launch_bounds__(THREADS, 8)
landmarks_fused(const float* __restrict__ pred,
                const float* __restrict__ lm,
                const float* __restrict__ bell,
                float* __restrict__ out,
                int n_bl, float inv_n)
{
    const int bl = blockIdx.x;
    const float4* img = reinterpret_cast<const float4*>(pred + (size_t)bl * (H_DIM * W_DIM));

    // landmarks: [...,0] = y_r (cols of heatmap / bell col), [...,1] = x_r (rows)
    const int yr = (int)rintf(__ldg(&lm[2 * bl + 0]));
    const int xr = (int)rintf(__ldg(&lm[2 * bl + 1]));
    const int xoff = HALF - xr;   // bell row index ix = h + xoff
    const int yoff = HALF - yr;   // bell col index iy = w + yoff

    const int lane = threadIdx.x & 31;
    const int wid  = threadIdx.x >> 5;

    const int j0 = lane;          // col4 indices covered by this lane
    const int j1 = lane + 32;
    const bool has1 = (j1 < ROWF4);
    const int iyb0 = 4 * j0 + yoff;
    const int iyb1 = 4 * j1 + yoff;

    float acc = 0.0f;

    #pragma unroll 2
    for (int r = 0; r < ROWS_PW; ++r) {
        const int h = wid + NWARP * r;
        const float4* row = img + h * ROWF4;

        // Front-batch the two row loads (streaming, no L2 reuse).
        const float4 p0 = __ldcs(&row[j0]);
        float4 p1 = make_float4(0.f, 0.f, 0.f, 0.f);
        if (has1) p1 = __ldcs(&row[j1]);

        const int ix = h + xoff;
        if ((unsigned)ix < (unsigned)DELTA) {   // warp-uniform branch
            const float* brow = bell + (ix << 7);

            float t0 = 0.f, t1 = 0.f, t2 = 0.f, t3 = 0.f;
            if ((unsigned)(iyb0 + 0) < (unsigned)DELTA) t0 = __ldg(&brow[iyb0 + 0]);
            if ((unsigned)(iyb0 + 1) < (unsigned)DELTA) t1 = __ldg(&brow[iyb0 + 1]);
            if ((unsigned)(iyb0 + 2) < (unsigned)DELTA) t2 = __ldg(&brow[iyb0 + 2]);
            if ((unsigned)(iyb0 + 3) < (unsigned)DELTA) t3 = __ldg(&brow[iyb0 + 3]);
            float d;
            d = p0.x - t0; acc = fmaf(d, d, acc);
            d = p0.y - t1; acc = fmaf(d, d, acc);
            d = p0.z - t2; acc = fmaf(d, d, acc);
            d = p0.w - t3; acc = fmaf(d, d, acc);

            float u0 = 0.f, u1 = 0.f, u2 = 0.f, u3 = 0.f;
            if (has1) {
                if ((unsigned)(iyb1 + 0) < (unsigned)DELTA) u0 = __ldg(&brow[iyb1 + 0]);
                if ((unsigned)(iyb1 + 1) < (unsigned)DELTA) u1 = __ldg(&brow[iyb1 + 1]);
                if ((unsigned)(iyb1 + 2) < (unsigned)DELTA) u2 = __ldg(&brow[iyb1 + 2]);
                if ((unsigned)(iyb1 + 3) < (unsigned)DELTA) u3 = __ldg(&brow[iyb1 + 3]);
            }
            d = p1.x - u0; acc = fmaf(d, d, acc);
            d = p1.y - u1; acc = fmaf(d, d, acc);
            d = p1.z - u2; acc = fmaf(d, d, acc);
            d = p1.w - u3; acc = fmaf(d, d, acc);
        } else {
            acc = fmaf(p0.x, p0.x, acc);
            acc = fmaf(p0.y, p0.y, acc);
            acc = fmaf(p0.z, p0.z, acc);
            acc = fmaf(p0.w, p0.w, acc);
            acc = fmaf(p1.x, p1.x, acc);
            acc = fmaf(p1.y, p1.y, acc);
            acc = fmaf(p1.z, p1.z, acc);
            acc = fmaf(p1.w, p1.w, acc);
        }
    }

    __shared__ float s[NWARP];
    const float bsum = blockReduce(acc, s);

    __shared__ bool amLast;
    if (threadIdx.x == 0) {
        g_partials[bl] = bsum;
        __threadfence();
        const unsigned prev = atomicAdd(&g_count, 1u);
        amLast = (prev == (unsigned)(gridDim.x - 1));
    }
    __syncthreads();

    if (amLast) {
        // Deterministic final reduction: fixed index order every run.
        float tot = 0.0f;
        for (int i = threadIdx.x; i < n_bl; i += THREADS)
            tot += __ldcg(&g_partials[i]);
        __syncthreads();   // reuse s[] safely
        const float t = blockReduce(tot, s);
        if (threadIdx.x == 0) {
            out[0] = t * inv_n;
            g_count = 0;   // reset for next graph replay
        }
    }
}

extern "C" void kernel_launch(void* const* d_in, const int* in_sizes, int n_in,
                              void* d_out, int out_size)
{
    const float* pred = (const float*)d_in[0];  // (B, L, 224, 224)
    const float* lm   = (const float*)d_in[1];  // (B, L, 2)
    const float* bell = (const float*)d_in[2];  // (128, 128)
    float* out = (float*)d_out;

    const int n_bl = in_sizes[1] / 2;           // B*L = 1088
    const float inv_n = 1.0f / ((float)n_bl * (float)(H_DIM * W_DIM));

    landmarks_fused<<<n_bl, THREADS>>>(pred, lm, bell, out, n_bl, inv_n);
}